// round 6
// baseline (speedup 1.0000x reference)
#include <cuda_runtime.h>
#include <cuda_bf16.h>

#define VOCAB 50257
#define BATCH 512
#define SEQ   512
#define TPB   256
#define GRID  BATCH   // 512 blocks, all co-resident (capacity >= 592 even at 4 blk/SM)

// Interleaved weight table: g_Wp[v] = {W[0][v], W[1][v]} -> ONE 8B gather/token.
__device__ float2 g_Wp[VOCAB];
// Monotonic epoch barrier counter (never reset; modular-safe compare below).
__device__ unsigned g_bar = 0;

__global__ __launch_bounds__(TPB) void bow_fused_kernel(
    const int*   __restrict__ ids,
    const float* __restrict__ W,     // [2, VOCAB]
    const float* __restrict__ bias,  // [2]
    float*       __restrict__ out)   // [BATCH, 2]
{
    const int tid = threadIdx.x;

    // ---- Phase 1: build interleaved table (131072 threads cover 50257 slots).
    {
        const int v = blockIdx.x * TPB + tid;
        if (v < VOCAB)
            g_Wp[v] = make_float2(__ldg(W + v), __ldg(W + VOCAB + v));
    }

    // ---- Software global barrier (all GRID blocks are co-resident).
    __threadfence();          // table stores visible at gpu scope
    __syncthreads();
    if (tid == 0) {
        unsigned ticket = atomicAdd(&g_bar, 1u);
        unsigned target = (ticket / GRID + 1u) * GRID;   // this launch's epoch end
        unsigned v;
        do {
            asm volatile("ld.acquire.gpu.global.u32 %0, [%1];"
                         : "=r"(v) : "l"(&g_bar));
        } while ((int)(v - target) < 0);                 // wrap-safe compare
    }
    __syncthreads();

    // ---- Phase 2: one row per block, 2 tokens/thread, one 8B gather/token.
    const int row = blockIdx.x;
    const int2 t2 = *reinterpret_cast<const int2*>(ids + (row << 9) + tid * 2);

    float2 w0 = (t2.x != 0) ? g_Wp[t2.x] : make_float2(0.f, 0.f);
    float2 w1 = (t2.y != 0) ? g_Wp[t2.y] : make_float2(0.f, 0.f);

    float s0 = w0.x + w1.x;
    float s1 = w0.y + w1.y;

    #pragma unroll
    for (int o = 16; o > 0; o >>= 1) {
        s0 += __shfl_down_sync(0xffffffffu, s0, o);
        s1 += __shfl_down_sync(0xffffffffu, s1, o);
    }

    __shared__ float2 sm[TPB / 32];
    const int w = tid >> 5, l = tid & 31;
    if (l == 0) sm[w] = make_float2(s0, s1);
    __syncthreads();

    if (tid == 0) {
        float r0 = 0.f, r1 = 0.f;
        #pragma unroll
        for (int i = 0; i < TPB / 32; i++) { r0 += sm[i].x; r1 += sm[i].y; }
        float2 r;
        r.x = r0 + __ldg(bias + 0);
        r.y = r1 + __ldg(bias + 1);
        *reinterpret_cast<float2*>(out + row * 2) = r;
    }
}

extern "C" void kernel_launch(void* const* d_in, const int* in_sizes, int n_in,
                              void* d_out, int out_size) {
    const int*   ids  = (const int*)  d_in[0];  // input_ids [512, 512] int32
    const float* W    = (const float*)d_in[1];  // W [2, 50257] fp32
    const float* bias = (const float*)d_in[2];  // b [2] fp32
    float*       out  = (float*)d_out;          // logits [512, 2] fp32

    bow_fused_kernel<<<GRID, TPB>>>(ids, W, bias, out);
}

// round 7
// speedup vs baseline: 1.0236x; 1.0236x over previous
#include <cuda_runtime.h>
#include <cuda_bf16.h>

#define VOCAB 50257
#define BATCH 512
#define SEQ   512
#define TPB   128          // 4 tokens per thread

// W footprint: 2*50257 floats = 402,056 B = 3142 lines of 128B (ceil).
#define W_LINES 3142
#define LINES_PER_BLOCK 8  // 512 blocks * 8 = 4096 >= 3142

__global__ __launch_bounds__(TPB) void bow_logits_kernel(
    const int*   __restrict__ ids,
    const float* __restrict__ W,     // [2, VOCAB]
    const float* __restrict__ bias,  // [2]
    float*       __restrict__ out)   // [BATCH, 2]
{
    const int row = blockIdx.x;
    const int tid = threadIdx.x;

    // ---- L2 prefetch of W, issued BEFORE the dependent chain. Covers all of
    // W chip-wide (one request per 128B line, no duplication) so the gathers
    // below hit L2 instead of making a second serialized DRAM round-trip.
    if (tid < LINES_PER_BLOCK) {
        const int line = row * LINES_PER_BLOCK + tid;
        if (line < W_LINES) {
            const char* p = reinterpret_cast<const char*>(W) + (size_t)line * 128;
            asm volatile("prefetch.global.L2 [%0];" :: "l"(p));
        }
    }

    // ---- 4 tokens per thread via one coalesced 16B load (DRAM, overlapped
    // with the W prefetch above).
    const int4 t4 = *reinterpret_cast<const int4*>(ids + (row << 9) + tid * 4);

    const float* __restrict__ W0 = W;
    const float* __restrict__ W1 = W + VOCAB;

    // 8 independent gathers, front-batched.
    float a0 = (t4.x != 0) ? __ldg(W0 + t4.x) : 0.f;
    float a1 = (t4.y != 0) ? __ldg(W0 + t4.y) : 0.f;
    float a2 = (t4.z != 0) ? __ldg(W0 + t4.z) : 0.f;
    float a3 = (t4.w != 0) ? __ldg(W0 + t4.w) : 0.f;
    float b0 = (t4.x != 0) ? __ldg(W1 + t4.x) : 0.f;
    float b1 = (t4.y != 0) ? __ldg(W1 + t4.y) : 0.f;
    float b2 = (t4.z != 0) ? __ldg(W1 + t4.z) : 0.f;
    float b3 = (t4.w != 0) ? __ldg(W1 + t4.w) : 0.f;

    float s0 = (a0 + a1) + (a2 + a3);
    float s1 = (b0 + b1) + (b2 + b3);

    // Warp reduction.
    #pragma unroll
    for (int o = 16; o > 0; o >>= 1) {
        s0 += __shfl_down_sync(0xffffffffu, s0, o);
        s1 += __shfl_down_sync(0xffffffffu, s1, o);
    }

    __shared__ float2 sm[TPB / 32];
    const int w = tid >> 5, l = tid & 31;
    if (l == 0) sm[w] = make_float2(s0, s1);
    __syncthreads();

    if (tid == 0) {
        float r0 = 0.f, r1 = 0.f;
        #pragma unroll
        for (int i = 0; i < TPB / 32; i++) { r0 += sm[i].x; r1 += sm[i].y; }
        float2 r;
        r.x = r0 + __ldg(bias + 0);
        r.y = r1 + __ldg(bias + 1);
        *reinterpret_cast<float2*>(out + row * 2) = r;
    }
}

extern "C" void kernel_launch(void* const* d_in, const int* in_sizes, int n_in,
                              void* d_out, int out_size) {
    const int*   ids  = (const int*)  d_in[0];  // input_ids [512, 512] int32
    const float* W    = (const float*)d_in[1];  // W [2, 50257] fp32
    const float* bias = (const float*)d_in[2];  // b [2] fp32
    float*       out  = (float*)d_out;          // logits [512, 2] fp32

    bow_logits_kernel<<<BATCH, TPB>>>(ids, W, bias, out);
}